// round 1
// baseline (speedup 1.0000x reference)
#include <cuda_runtime.h>

// ---------------- problem constants ----------------
namespace cfg {
constexpr int B  = 2;
constexpr int S  = 8192;
constexpr int D  = 512;
constexpr int H  = 8;
constexpr int W  = 256;
constexpr int HD = 64;
constexpr int C  = S / W;     // 32
constexpr int BH = B * H;     // 16
constexpr int BS = B * S;     // 16384
}

// scratch for projected q,k,v in (BH, S, HD) layout  (3 x 32 MB)
__device__ float g_q[cfg::BH * cfg::S * cfg::HD];
__device__ float g_k[cfg::BH * cfg::S * cfg::HD];
__device__ float g_v[cfg::BH * cfg::S * cfg::HD];

// ---------------------------------------------------------------------------
// Kernel 1: QKV projection GEMM.  y = x @ Wm + b (q additionally scaled).
// Tile 64x64, K-step 16, 256 threads, 4x4 register tile per thread.
// blockIdx.z selects q / k / v.
// ---------------------------------------------------------------------------
__global__ __launch_bounds__(256) void qkv_gemm(
    const float* __restrict__ x,
    const float* __restrict__ Wq, const float* __restrict__ bq,
    const float* __restrict__ Wk, const float* __restrict__ bk,
    const float* __restrict__ Wv, const float* __restrict__ bv)
{
    using namespace cfg;
    const float* Wm; const float* bias; float* out; float scale;
    if (blockIdx.z == 0)      { Wm = Wq; bias = bq; out = g_q; scale = 0.125f; }
    else if (blockIdx.z == 1) { Wm = Wk; bias = bk; out = g_k; scale = 1.0f;  }
    else                      { Wm = Wv; bias = bv; out = g_v; scale = 1.0f;  }

    __shared__ float As[16][68];   // As[k][m]  (x tile, transposed)
    __shared__ float Bs[16][68];   // Bs[k][n]  (W tile)

    const int t  = threadIdx.x;
    const int ty = t >> 4, tx = t & 15;
    const int m0 = blockIdx.y * 64;
    const int n0 = blockIdx.x * 64;

    const int lm = t >> 2;          // 0..63 : row of x tile this thread loads
    const int lk = (t & 3) * 4;     // 0,4,8,12
    const int bkr = t >> 4;         // 0..15 : row of W tile
    const int bn  = (t & 15) * 4;   // 0..60

    float acc[4][4] = {};

    for (int k0 = 0; k0 < D; k0 += 16) {
        float4 a4 = *(const float4*)&x[(size_t)(m0 + lm) * D + k0 + lk];
        As[lk + 0][lm] = a4.x; As[lk + 1][lm] = a4.y;
        As[lk + 2][lm] = a4.z; As[lk + 3][lm] = a4.w;
        *(float4*)&Bs[bkr][bn] =
            *(const float4*)&Wm[(size_t)(k0 + bkr) * D + n0 + bn];
        __syncthreads();
        #pragma unroll
        for (int kk = 0; kk < 16; kk++) {
            float4 av = *(const float4*)&As[kk][ty * 4];
            float4 bw = *(const float4*)&Bs[kk][tx * 4];
            const float a[4] = {av.x, av.y, av.z, av.w};
            const float b[4] = {bw.x, bw.y, bw.z, bw.w};
            #pragma unroll
            for (int i = 0; i < 4; i++)
                #pragma unroll
                for (int j = 0; j < 4; j++)
                    acc[i][j] = fmaf(a[i], b[j], acc[i][j]);
        }
        __syncthreads();
    }

    // tile covers exactly one head's 64 columns
    const int h = n0 / HD;
    float4 b4 = *(const float4*)&bias[n0 + tx * 4];
    const float bb[4] = {b4.x, b4.y, b4.z, b4.w};
    #pragma unroll
    for (int i = 0; i < 4; i++) {
        int m = m0 + ty * 4 + i;
        int bb_idx = m / S, s = m % S;
        float4 o4;
        o4.x = (acc[i][0] + bb[0]) * scale;
        o4.y = (acc[i][1] + bb[1]) * scale;
        o4.z = (acc[i][2] + bb[2]) * scale;
        o4.w = (acc[i][3] + bb[3]) * scale;
        *(float4*)&out[(((size_t)(bb_idx * H + h) * S + s) * HD) + tx * 4] = o4;
    }
}

// ---------------------------------------------------------------------------
// Kernel 2: banded attention, flash-style online softmax.
// Block = 64 queries of chunk c (sub-tile qt), streams 9 key tiles of 64
// covering window y in [x0, x0 + 2W + 63] of the 3W neighbor-chunk window.
// ---------------------------------------------------------------------------
__global__ __launch_bounds__(256) void attn(float* __restrict__ out)
{
    using namespace cfg;
    extern __shared__ float sm[];
    float (*Qt)[68] = (float(*)[68])(sm);               // Qt[d][r]
    float (*Kt)[68] = (float(*)[68])(sm + 64 * 68);     // Kt[d][col]
    float (*Vs)[68] = (float(*)[68])(sm + 2 * 64 * 68); // Vs[col][d]
    float (*Pt)[68] = (float(*)[68])(sm + 3 * 64 * 68); // Pt[col][r]

    const int qt = blockIdx.x;        // 0..3  (64-query sub-tile within chunk)
    const int c  = blockIdx.y;        // 0..31 chunk
    const int bh = blockIdx.z;        // 0..15
    const int x0 = qt * 64;

    const float* qp = g_q + (size_t)bh * S * HD;
    const float* kp = g_k + (size_t)bh * S * HD;
    const float* vp = g_v + (size_t)bh * S * HD;

    const int t  = threadIdx.x;
    const int ty = t >> 4, tx = t & 15;
    const int lr  = t >> 2;           // 0..63 row/col for cooperative loads
    const int ld0 = (t & 3) * 16;     // base d

    // ---- load Q transposed (Qt[d][r]) ----
    {
        const float* src = &qp[(size_t)(c * W + x0 + lr) * HD];
        #pragma unroll
        for (int i = 0; i < 4; i++) {
            int d = ld0 + i * 4;
            float4 v4 = *(const float4*)&src[d];
            Qt[d + 0][lr] = v4.x; Qt[d + 1][lr] = v4.y;
            Qt[d + 2][lr] = v4.z; Qt[d + 3][lr] = v4.w;
        }
    }

    float o[4][4] = {};
    float mrow[4], lsum[4];
    #pragma unroll
    for (int i = 0; i < 4; i++) { mrow[i] = -1e30f; lsum[i] = 0.0f; }

    for (int kt = 0; kt < 9; kt++) {
        const int gb = (c - 1) * W + x0 + kt * 64;  // global pos of tile col 0
        if (gb >= S || gb + 64 <= 0) continue;      // fully out of sequence

        __syncthreads();   // previous PV done before overwriting K/V

        // ---- load K (transposed) and V tiles ----
        {
            int gpos = gb + lr;
            bool ok = (gpos >= 0) && (gpos < S);
            const float* ksrc = &kp[(size_t)gpos * HD];
            const float* vsrc = &vp[(size_t)gpos * HD];
            #pragma unroll
            for (int i = 0; i < 4; i++) {
                int d = ld0 + i * 4;
                float4 kv = ok ? *(const float4*)&ksrc[d] : make_float4(0,0,0,0);
                Kt[d + 0][lr] = kv.x; Kt[d + 1][lr] = kv.y;
                Kt[d + 2][lr] = kv.z; Kt[d + 3][lr] = kv.w;
                float4 vv = ok ? *(const float4*)&vsrc[d] : make_float4(0,0,0,0);
                *(float4*)&Vs[lr][d] = vv;
            }
        }
        __syncthreads();

        // ---- S = Q K^T (4x4 per thread) ----
        float sc[4][4] = {};
        #pragma unroll 8
        for (int kk = 0; kk < 64; kk++) {
            float4 av = *(const float4*)&Qt[kk][ty * 4];
            float4 bw = *(const float4*)&Kt[kk][tx * 4];
            const float a[4] = {av.x, av.y, av.z, av.w};
            const float b[4] = {bw.x, bw.y, bw.z, bw.w};
            #pragma unroll
            for (int i = 0; i < 4; i++)
                #pragma unroll
                for (int j = 0; j < 4; j++)
                    sc[i][j] = fmaf(a[i], b[j], sc[i][j]);
        }

        // ---- band + sequence mask ----
        #pragma unroll
        for (int i = 0; i < 4; i++) {
            int r = ty * 4 + i;                 // query row within sub-tile
            #pragma unroll
            for (int j = 0; j < 4; j++) {
                int cc   = tx * 4 + j;
                int ywin = kt * 64 + cc;        // key offset relative to x0
                int gpos = gb + cc;
                bool ok = (ywin >= r) && (ywin <= r + 2 * W) &&
                          (gpos >= 0) && (gpos < S);
                if (!ok) sc[i][j] = -1e30f;
            }
        }

        // ---- online softmax update (row spread over 16 lanes) ----
        #pragma unroll
        for (int i = 0; i < 4; i++) {
            float rm = fmaxf(fmaxf(sc[i][0], sc[i][1]),
                             fmaxf(sc[i][2], sc[i][3]));
            #pragma unroll
            for (int off = 8; off >= 1; off >>= 1)
                rm = fmaxf(rm, __shfl_xor_sync(0xffffffffu, rm, off));
            float mnew = fmaxf(mrow[i], rm);
            float corr = __expf(mrow[i] - mnew);
            float rs = 0.0f;
            #pragma unroll
            for (int j = 0; j < 4; j++) {
                sc[i][j] = __expf(sc[i][j] - mnew);
                rs += sc[i][j];
            }
            #pragma unroll
            for (int off = 8; off >= 1; off >>= 1)
                rs += __shfl_xor_sync(0xffffffffu, rs, off);
            lsum[i] = lsum[i] * corr + rs;
            mrow[i] = mnew;
            #pragma unroll
            for (int j = 0; j < 4; j++) o[i][j] *= corr;
        }

        // ---- write P transposed ----
        #pragma unroll
        for (int i = 0; i < 4; i++)
            #pragma unroll
            for (int j = 0; j < 4; j++)
                Pt[tx * 4 + j][ty * 4 + i] = sc[i][j];
        __syncthreads();

        // ---- O += P V ----
        #pragma unroll 8
        for (int col = 0; col < 64; col++) {
            float4 pv = *(const float4*)&Pt[col][ty * 4];
            float4 vv = *(const float4*)&Vs[col][tx * 4];
            const float p[4] = {pv.x, pv.y, pv.z, pv.w};
            const float v[4] = {vv.x, vv.y, vv.z, vv.w};
            #pragma unroll
            for (int i = 0; i < 4; i++)
                #pragma unroll
                for (int j = 0; j < 4; j++)
                    o[i][j] = fmaf(p[i], v[j], o[i][j]);
        }
    }

    // ---- epilogue: normalize and write (B,S,D) ----
    const int b = bh / H, h = bh % H;
    #pragma unroll
    for (int i = 0; i < 4; i++) {
        int sq = c * W + x0 + ty * 4 + i;
        float inv = 1.0f / lsum[i];
        float4 o4 = make_float4(o[i][0] * inv, o[i][1] * inv,
                                o[i][2] * inv, o[i][3] * inv);
        *(float4*)&out[((size_t)b * S + sq) * D + h * HD + tx * 4] = o4;
    }
}

// ---------------------------------------------------------------------------
extern "C" void kernel_launch(void* const* d_in, const int* in_sizes, int n_in,
                              void* d_out, int out_size)
{
    using namespace cfg;
    (void)in_sizes; (void)n_in; (void)out_size;
    const float* x  = (const float*)d_in[0];
    const float* Wq = (const float*)d_in[1];
    const float* bq = (const float*)d_in[2];
    const float* Wk = (const float*)d_in[3];
    const float* bk = (const float*)d_in[4];
    const float* Wv = (const float*)d_in[5];
    const float* bv = (const float*)d_in[6];
    float* out = (float*)d_out;

    qkv_gemm<<<dim3(D / 64, BS / 64, 3), 256>>>(x, Wq, bq, Wk, bk, Wv, bv);

    const int smem_bytes = 4 * 64 * 68 * (int)sizeof(float);  // 69632 B
    cudaFuncSetAttribute(attn, cudaFuncAttributeMaxDynamicSharedMemorySize,
                         smem_bytes);
    attn<<<dim3(4, C, BH), 256, smem_bytes>>>(out);
}

// round 3
// speedup vs baseline: 2.5376x; 2.5376x over previous
#include <cuda_runtime.h>
#include <cstdint>

// ---------------- problem constants ----------------
namespace cfg {
constexpr int B  = 2;
constexpr int S  = 8192;
constexpr int D  = 512;
constexpr int H  = 8;
constexpr int W  = 256;
constexpr int HD = 64;
constexpr int C  = S / W;     // 32
constexpr int BH = B * H;     // 16
constexpr int BS = B * S;     // 16384
}

// scratch for projected q,k,v in (BH, S, HD) layout  (3 x 32 MB)
__device__ float g_q[cfg::BH * cfg::S * cfg::HD];
__device__ float g_k[cfg::BH * cfg::S * cfg::HD];
__device__ float g_v[cfg::BH * cfg::S * cfg::HD];

// ------------------- mma.sync helpers (sm_80+ path) ------------------------
__device__ __forceinline__ uint32_t f2tf32(float f) {
    uint32_t r;
    asm("cvt.rna.tf32.f32 %0, %1;" : "=r"(r) : "f"(f));
    return r;
}
// D(16x8) += A(16x8) * B(8x8); A row-major frag, B col-major frag.
__device__ __forceinline__ void mma_tf32(float* c, const uint32_t* a,
                                         const uint32_t* b) {
    asm volatile(
        "mma.sync.aligned.m16n8k8.row.col.f32.tf32.tf32.f32 "
        "{%0,%1,%2,%3}, {%4,%5,%6,%7}, {%8,%9}, {%0,%1,%2,%3};"
        : "+f"(c[0]), "+f"(c[1]), "+f"(c[2]), "+f"(c[3])
        : "r"(a[0]), "r"(a[1]), "r"(a[2]), "r"(a[3]), "r"(b[0]), "r"(b[1]));
}

// ---------------------------------------------------------------------------
// Kernel 1: QKV projection, tf32 mma.sync.
// CTA tile M=128, N=128, K chunk 32. 256 threads = 8 warps (4 m x 2 n),
// warp tile 32x64 = 2(m16) x 8(n8) mma tiles.
// ---------------------------------------------------------------------------
__global__ __launch_bounds__(256) void qkv_mma(
    const float* __restrict__ x,
    const float* __restrict__ Wq, const float* __restrict__ bq,
    const float* __restrict__ Wk, const float* __restrict__ bk,
    const float* __restrict__ Wv, const float* __restrict__ bv)
{
    using namespace cfg;
    __shared__ uint32_t As[128][36];   // x tile   [m][k] (+4 pad)
    __shared__ uint32_t Bs[32][132];   // W tile   [k][n] (+4 pad)

    const int mat = blockIdx.z;
    const float* Wm   = (mat == 0) ? Wq : (mat == 1) ? Wk : Wv;
    const float* bias = (mat == 0) ? bq : (mat == 1) ? bk : bv;
    float* outp       = (mat == 0) ? g_q : (mat == 1) ? g_k : g_v;
    const float scale = (mat == 0) ? 0.125f : 1.0f;

    const int t = threadIdx.x;
    const int wid = t >> 5, lane = t & 31;
    const int wm = wid & 3, wn = wid >> 2;
    const int r = lane >> 2, q = lane & 3;

    const int m0 = blockIdx.y * 128;
    const int n0 = blockIdx.x * 128;

    float acc[2][8][4] = {};

    for (int k0 = 0; k0 < D; k0 += 32) {
        // ---- stage A: 128 x 32 floats (1024 float4 slots) ----
        #pragma unroll
        for (int i = 0; i < 4; i++) {
            int idx = t + 256 * i;
            int row = idx >> 3, j = idx & 7;
            float4 v = *(const float4*)&x[(size_t)(m0 + row) * D + k0 + j * 4];
            uint4 c = make_uint4(f2tf32(v.x), f2tf32(v.y),
                                 f2tf32(v.z), f2tf32(v.w));
            *(uint4*)&As[row][j * 4] = c;
        }
        // ---- stage B: 32 x 128 floats ----
        #pragma unroll
        for (int i = 0; i < 4; i++) {
            int idx = t + 256 * i;
            int row = idx >> 5, j = idx & 31;
            float4 v = *(const float4*)&Wm[(size_t)(k0 + row) * D + n0 + j * 4];
            uint4 c = make_uint4(f2tf32(v.x), f2tf32(v.y),
                                 f2tf32(v.z), f2tf32(v.w));
            *(uint4*)&Bs[row][j * 4] = c;
        }
        __syncthreads();

        #pragma unroll
        for (int kk = 0; kk < 4; kk++) {
            uint32_t a[2][4];
            #pragma unroll
            for (int mt = 0; mt < 2; mt++) {
                int rb = wm * 32 + mt * 16;
                a[mt][0] = As[rb + r][kk * 8 + q];
                a[mt][1] = As[rb + r + 8][kk * 8 + q];
                a[mt][2] = As[rb + r][kk * 8 + q + 4];
                a[mt][3] = As[rb + r + 8][kk * 8 + q + 4];
            }
            #pragma unroll
            for (int nt = 0; nt < 8; nt++) {
                uint32_t b[2];
                int nb = wn * 64 + nt * 8 + r;
                b[0] = Bs[kk * 8 + q][nb];
                b[1] = Bs[kk * 8 + q + 4][nb];
                mma_tf32(acc[0][nt], a[0], b);
                mma_tf32(acc[1][nt], a[1], b);
            }
        }
        __syncthreads();
    }

    // ---- epilogue: bias + scale, write head-split layout ----
    #pragma unroll
    for (int mt = 0; mt < 2; mt++) {
        #pragma unroll
        for (int half = 0; half < 2; half++) {       // c0/c1 vs c2/c3
            int m = m0 + wm * 32 + mt * 16 + r + half * 8;
            int b = m >> 13, s = m & (S - 1);
            #pragma unroll
            for (int nt = 0; nt < 8; nt++) {
                int nc = n0 + wn * 64 + nt * 8 + 2 * q;
                int h = nc >> 6, hc = nc & 63;
                float2 o;
                o.x = (acc[mt][nt][half * 2 + 0] + bias[nc])     * scale;
                o.y = (acc[mt][nt][half * 2 + 1] + bias[nc + 1]) * scale;
                *(float2*)&outp[(((size_t)(b * H + h) * S + s) * HD) + hc] = o;
            }
        }
    }
}

// ---------------------------------------------------------------------------
// Kernel 2: banded attention, flash softmax, tf32 mma.sync.
// 128 threads (4 warps). Q tile = 64 rows; 9 streamed key tiles of 64.
// Warp w owns rows [w*16, w*16+16).
// ---------------------------------------------------------------------------
namespace at {
constexpr int PAD = 68;
constexpr int SMEM_BYTES = 3 * 64 * PAD * 4;   // Ks, Vs, Ps  (52224 B)
}

__global__ __launch_bounds__(128) void attn(float* __restrict__ out)
{
    using namespace cfg;
    using namespace at;
    extern __shared__ uint32_t smd[];
    uint32_t (*Ks)[PAD] = (uint32_t(*)[PAD])(smd);               // [key][d]
    uint32_t (*Vs)[PAD] = (uint32_t(*)[PAD])(smd + 64 * PAD);    // [key][d]
    uint32_t (*Ps)[PAD] = (uint32_t(*)[PAD])(smd + 2 * 64 * PAD);// [row][col]

    const int qt = blockIdx.x;        // 64-query sub-tile within chunk
    const int c  = blockIdx.y;
    const int bh = blockIdx.z;
    const int x0 = qt * 64;

    const float* qp = g_q + (size_t)bh * S * HD;
    const float* kp = g_k + (size_t)bh * S * HD;
    const float* vp = g_v + (size_t)bh * S * HD;

    const int t = threadIdx.x;
    const int wid = t >> 5, lane = t & 31;
    const int r = lane >> 2, q = lane & 3;
    const int wr = wid * 16;          // warp row base

    // ---- stage Q into Ps, then lift fragments to registers ----
    #pragma unroll
    for (int i = 0; i < 8; i++) {
        int idx = t + 128 * i;                    // 1024 float4 slots
        int row = idx >> 4, j = idx & 15;
        float4 v = *(const float4*)&qp[(size_t)(c * W + x0 + row) * HD + j * 4];
        *(uint4*)&Ps[row][j * 4] = make_uint4(f2tf32(v.x), f2tf32(v.y),
                                              f2tf32(v.z), f2tf32(v.w));
    }
    __syncthreads();
    uint32_t qa[8][4];
    #pragma unroll
    for (int kk = 0; kk < 8; kk++) {
        qa[kk][0] = Ps[wr + r][kk * 8 + q];
        qa[kk][1] = Ps[wr + r + 8][kk * 8 + q];
        qa[kk][2] = Ps[wr + r][kk * 8 + q + 4];
        qa[kk][3] = Ps[wr + r + 8][kk * 8 + q + 4];
    }

    float o[8][4] = {};
    float mrow0 = -1e30f, mrow1 = -1e30f, lsum0 = 0.0f, lsum1 = 0.0f;

    for (int kt = 0; kt < 9; kt++) {
        const int gb = (c - 1) * W + x0 + kt * 64;
        if (gb >= S || gb + 64 <= 0) continue;

        __syncthreads();   // prior PV / Q-frag reads done before overwrite

        // ---- stage K, V tiles [key][d] ----
        #pragma unroll
        for (int i = 0; i < 8; i++) {
            int idx = t + 128 * i;
            int row = idx >> 4, j = idx & 15;
            int gpos = gb + row;
            bool ok = (gpos >= 0) && (gpos < S);
            float4 kv = ok ? *(const float4*)&kp[(size_t)gpos * HD + j * 4]
                           : make_float4(0, 0, 0, 0);
            float4 vv = ok ? *(const float4*)&vp[(size_t)gpos * HD + j * 4]
                           : make_float4(0, 0, 0, 0);
            *(uint4*)&Ks[row][j * 4] = make_uint4(f2tf32(kv.x), f2tf32(kv.y),
                                                  f2tf32(kv.z), f2tf32(kv.w));
            *(uint4*)&Vs[row][j * 4] = make_uint4(f2tf32(vv.x), f2tf32(vv.y),
                                                  f2tf32(vv.z), f2tf32(vv.w));
        }
        __syncthreads();

        // ---- S = Q K^T : B-frag b0 = K[key=nt*8+r][d=kk*8+q] ----
        float sc[8][4] = {};
        #pragma unroll
        for (int kk = 0; kk < 8; kk++) {
            #pragma unroll
            for (int nt = 0; nt < 8; nt++) {
                uint32_t b[2];
                b[0] = Ks[nt * 8 + r][kk * 8 + q];
                b[1] = Ks[nt * 8 + r][kk * 8 + q + 4];
                mma_tf32(sc[nt], qa[kk], b);
            }
        }

        // ---- band + sequence mask ----
        const int row0 = wr + r, row1 = row0 + 8;
        #pragma unroll
        for (int nt = 0; nt < 8; nt++) {
            #pragma unroll
            for (int j = 0; j < 2; j++) {
                int col  = nt * 8 + 2 * q + j;
                int ywin = kt * 64 + col;
                int gpos = gb + col;
                bool inseq = (gpos >= 0) && (gpos < S);
                if (!(inseq && ywin >= row0 && ywin <= row0 + 2 * W))
                    sc[nt][j] = -1e30f;
                if (!(inseq && ywin >= row1 && ywin <= row1 + 2 * W))
                    sc[nt][2 + j] = -1e30f;
            }
        }

        // ---- online softmax (rows live in lane quads) ----
        float rm0 = -1e30f, rm1 = -1e30f;
        #pragma unroll
        for (int nt = 0; nt < 8; nt++) {
            rm0 = fmaxf(rm0, fmaxf(sc[nt][0], sc[nt][1]));
            rm1 = fmaxf(rm1, fmaxf(sc[nt][2], sc[nt][3]));
        }
        #pragma unroll
        for (int off = 1; off <= 2; off <<= 1) {
            rm0 = fmaxf(rm0, __shfl_xor_sync(0xffffffffu, rm0, off));
            rm1 = fmaxf(rm1, __shfl_xor_sync(0xffffffffu, rm1, off));
        }
        float mn0 = fmaxf(mrow0, rm0), mn1 = fmaxf(mrow1, rm1);
        float cr0 = __expf(mrow0 - mn0), cr1 = __expf(mrow1 - mn1);
        float rs0 = 0.0f, rs1 = 0.0f;
        #pragma unroll
        for (int nt = 0; nt < 8; nt++) {
            sc[nt][0] = __expf(sc[nt][0] - mn0);
            sc[nt][1] = __expf(sc[nt][1] - mn0);
            sc[nt][2] = __expf(sc[nt][2] - mn1);
            sc[nt][3] = __expf(sc[nt][3] - mn1);
            rs0 += sc[nt][0] + sc[nt][1];
            rs1 += sc[nt][2] + sc[nt][3];
        }
        #pragma unroll
        for (int off = 1; off <= 2; off <<= 1) {
            rs0 += __shfl_xor_sync(0xffffffffu, rs0, off);
            rs1 += __shfl_xor_sync(0xffffffffu, rs1, off);
        }
        lsum0 = lsum0 * cr0 + rs0;
        lsum1 = lsum1 * cr1 + rs1;
        mrow0 = mn0; mrow1 = mn1;
        #pragma unroll
        for (int nt = 0; nt < 8; nt++) {
            o[nt][0] *= cr0; o[nt][1] *= cr0;
            o[nt][2] *= cr1; o[nt][3] *= cr1;
        }

        // ---- store P (tf32) ----
        #pragma unroll
        for (int nt = 0; nt < 8; nt++) {
            int col = nt * 8 + 2 * q;
            Ps[row0][col]     = f2tf32(sc[nt][0]);
            Ps[row0][col + 1] = f2tf32(sc[nt][1]);
            Ps[row1][col]     = f2tf32(sc[nt][2]);
            Ps[row1][col + 1] = f2tf32(sc[nt][3]);
        }
        __syncthreads();

        // ---- O += P V : A-frag from Ps, B-frag b0 = V[key=kk*8+q][d=nt*8+r]
        #pragma unroll
        for (int kk = 0; kk < 8; kk++) {
            uint32_t pa[4];
            pa[0] = Ps[wr + r][kk * 8 + q];
            pa[1] = Ps[wr + r + 8][kk * 8 + q];
            pa[2] = Ps[wr + r][kk * 8 + q + 4];
            pa[3] = Ps[wr + r + 8][kk * 8 + q + 4];
            #pragma unroll
            for (int nt = 0; nt < 8; nt++) {
                uint32_t b[2];
                b[0] = Vs[kk * 8 + q][nt * 8 + r];
                b[1] = Vs[kk * 8 + q + 4][nt * 8 + r];
                mma_tf32(o[nt], pa, b);
            }
        }
    }

    // ---- epilogue ----
    const int b = bh / H, h = bh % H;
    const float inv0 = 1.0f / lsum0, inv1 = 1.0f / lsum1;
    const int sq0 = c * W + x0 + wr + r;
    const int sq1 = sq0 + 8;
    #pragma unroll
    for (int nt = 0; nt < 8; nt++) {
        int col = nt * 8 + 2 * q;
        float2 v0 = make_float2(o[nt][0] * inv0, o[nt][1] * inv0);
        float2 v1 = make_float2(o[nt][2] * inv1, o[nt][3] * inv1);
        *(float2*)&out[((size_t)b * S + sq0) * D + h * HD + col] = v0;
        *(float2*)&out[((size_t)b * S + sq1) * D + h * HD + col] = v1;
    }
}

// ---------------------------------------------------------------------------
extern "C" void kernel_launch(void* const* d_in, const int* in_sizes, int n_in,
                              void* d_out, int out_size)
{
    using namespace cfg;
    (void)in_sizes; (void)n_in; (void)out_size;
    const float* x  = (const float*)d_in[0];
    const float* Wq = (const float*)d_in[1];
    const float* bq = (const float*)d_in[2];
    const float* Wk = (const float*)d_in[3];
    const float* bk = (const float*)d_in[4];
    const float* Wv = (const float*)d_in[5];
    const float* bv = (const float*)d_in[6];
    float* out = (float*)d_out;

    qkv_mma<<<dim3(D / 128, BS / 128, 3), 256>>>(x, Wq, bq, Wk, bk, Wv, bv);

    cudaFuncSetAttribute(attn, cudaFuncAttributeMaxDynamicSharedMemorySize,
                         at::SMEM_BYTES);
    attn<<<dim3(4, C, BH), 128, at::SMEM_BYTES>>>(out);
}

// round 5
// speedup vs baseline: 2.8572x; 1.1260x over previous
#include <cuda_runtime.h>
#include <cstdint>

// ---------------- problem constants ----------------
namespace cfg {
constexpr int B  = 2;
constexpr int S  = 8192;
constexpr int D  = 512;
constexpr int H  = 8;
constexpr int W  = 256;
constexpr int HD = 64;
constexpr int BH = B * H;     // 16
constexpr int BS = B * S;     // 16384
}

// scratch for projected q,k,v in (BH, S, HD) layout  (3 x 32 MB)
__device__ float g_q[cfg::BH * cfg::S * cfg::HD];
__device__ float g_k[cfg::BH * cfg::S * cfg::HD];
__device__ float g_v[cfg::BH * cfg::S * cfg::HD];

// ------------------- mma.sync helpers ------------------------
__device__ __forceinline__ uint32_t f2tf32(float f) {
    uint32_t r;
    asm("cvt.rna.tf32.f32 %0, %1;" : "=r"(r) : "f"(f));
    return r;
}
__device__ __forceinline__ void mma_tf32(float* c, const uint32_t* a,
                                         const uint32_t* b) {
    asm volatile(
        "mma.sync.aligned.m16n8k8.row.col.f32.tf32.tf32.f32 "
        "{%0,%1,%2,%3}, {%4,%5,%6,%7}, {%8,%9}, {%0,%1,%2,%3};"
        : "+f"(c[0]), "+f"(c[1]), "+f"(c[2]), "+f"(c[3])
        : "r"(a[0]), "r"(a[1]), "r"(a[2]), "r"(a[3]), "r"(b[0]), "r"(b[1]));
}
__device__ __forceinline__ uint4 cvt4(float4 v) {
    return make_uint4(f2tf32(v.x), f2tf32(v.y), f2tf32(v.z), f2tf32(v.w));
}

// ---------------------------------------------------------------------------
// Kernel 1: QKV projection, tf32 mma.sync, double-buffered smem.
// CTA tile M=128, N=128, K chunk 32. 256 threads = 8 warps (4m x 2n),
// warp tile 32x64. A pitch 36 (banks 4r+q), B pitch 136 (banks 8q+r).
// ---------------------------------------------------------------------------
namespace qk {
constexpr int AP = 36, BP = 136;
constexpr int A_WORDS = 128 * AP;          // 4608
constexpr int B_WORDS = 32 * BP;           // 4352
constexpr int SMEM_BYTES = (2 * A_WORDS + 2 * B_WORDS) * 4;   // 71680
}

__global__ __launch_bounds__(256) void qkv_mma(
    const float* __restrict__ x,
    const float* __restrict__ Wq, const float* __restrict__ bq,
    const float* __restrict__ Wk, const float* __restrict__ bk,
    const float* __restrict__ Wv, const float* __restrict__ bv)
{
    using namespace cfg;
    using namespace qk;
    extern __shared__ uint32_t smq[];

    const int mat = blockIdx.z;
    const float* Wm   = (mat == 0) ? Wq : (mat == 1) ? Wk : Wv;
    const float* bias = (mat == 0) ? bq : (mat == 1) ? bk : bv;
    float* outp       = (mat == 0) ? g_q : (mat == 1) ? g_k : g_v;
    const float scale = (mat == 0) ? 0.125f : 1.0f;

    const int t = threadIdx.x;
    const int wid = t >> 5, lane = t & 31;
    const int wm = wid & 3, wn = wid >> 2;
    const int r = lane >> 2, q = lane & 3;

    const int m0 = blockIdx.y * 128;
    const int n0 = blockIdx.x * 128;

    // loader indices
    const int aR = t >> 3, aJ = t & 7;    // A rows aR + 32*i, col word aJ*4
    const int bR = t >> 5, bJ = t & 31;   // B rows bR + 8*i,  col word bJ*4
    const float* aPtr = x  + (size_t)(m0 + aR) * D + aJ * 4;
    const float* bPtr = Wm + (size_t)bR * D + n0 + bJ * 4;

    float4 ax[4], bx[4];
    #pragma unroll
    for (int i = 0; i < 4; i++) {
        ax[i] = *(const float4*)(aPtr + (size_t)32 * i * D);
        bx[i] = *(const float4*)(bPtr + (size_t)8 * i * D);
    }

    float acc[2][8][4] = {};

    #pragma unroll 1
    for (int ch = 0; ch < 16; ch++) {
        const int buf = ch & 1;
        uint32_t* A  = smq + buf * A_WORDS;
        uint32_t* Bb = smq + 2 * A_WORDS + buf * B_WORDS;

        #pragma unroll
        for (int i = 0; i < 4; i++) {
            *(uint4*)&A[(aR + 32 * i) * AP + aJ * 4]  = cvt4(ax[i]);
            *(uint4*)&Bb[(bR + 8 * i) * BP + bJ * 4]  = cvt4(bx[i]);
        }
        __syncthreads();

        if (ch < 15) {
            const int k0n = (ch + 1) * 32;
            #pragma unroll
            for (int i = 0; i < 4; i++) {
                ax[i] = *(const float4*)(aPtr + (size_t)32 * i * D + k0n);
                bx[i] = *(const float4*)(bPtr + (size_t)(k0n + 8 * i) * D);
            }
        }

        #pragma unroll
        for (int kk = 0; kk < 4; kk++) {
            uint32_t a[2][4];
            #pragma unroll
            for (int mt = 0; mt < 2; mt++) {
                const int rb = wm * 32 + mt * 16;
                a[mt][0] = A[(rb + r) * AP + kk * 8 + q];
                a[mt][1] = A[(rb + r + 8) * AP + kk * 8 + q];
                a[mt][2] = A[(rb + r) * AP + kk * 8 + q + 4];
                a[mt][3] = A[(rb + r + 8) * AP + kk * 8 + q + 4];
            }
            #pragma unroll
            for (int nt = 0; nt < 8; nt++) {
                uint32_t b[2];
                const int nb = wn * 64 + nt * 8 + r;
                b[0] = Bb[(kk * 8 + q) * BP + nb];
                b[1] = Bb[(kk * 8 + q + 4) * BP + nb];
                mma_tf32(acc[0][nt], a[0], b);
                mma_tf32(acc[1][nt], a[1], b);
            }
        }
    }

    // ---- epilogue: bias + scale, head-split layout ----
    #pragma unroll
    for (int mt = 0; mt < 2; mt++) {
        #pragma unroll
        for (int half = 0; half < 2; half++) {
            const int m = m0 + wm * 32 + mt * 16 + r + half * 8;
            const int b = m >> 13, s = m & (S - 1);
            #pragma unroll
            for (int nt = 0; nt < 8; nt++) {
                const int nc = n0 + wn * 64 + nt * 8 + 2 * q;
                const int h = nc >> 6, hc = nc & 63;
                float2 o;
                o.x = (acc[mt][nt][half * 2 + 0] + bias[nc])     * scale;
                o.y = (acc[mt][nt][half * 2 + 1] + bias[nc + 1]) * scale;
                *(float2*)&outp[(((size_t)(b * H + h) * S + s) * HD) + hc] = o;
            }
        }
    }
}

// ---------------------------------------------------------------------------
// Kernel 2: sliding-window attention (radius W=256), flash softmax,
// tf32 mma.sync. 256 threads = 8 warps; 128-query tile; 10 key tiles of 64,
// double-buffered. P stays in registers (quad shuffles -> PV A-fragments).
// Window coords: key = base + col, query = q0 + row, base = q0 - W, so the
// band condition is exactly col - row in [0, 2W].
// ---------------------------------------------------------------------------
namespace at {
constexpr int KP = 68, VP = 72;
constexpr int KW = 64 * KP;                 // 4352 words / buf
constexpr int VW = 64 * VP;                 // 4608 words / buf
constexpr int SMEM_BYTES = (2 * KW + 2 * VW) * 4;   // 71680
}

__global__ __launch_bounds__(256) void attn(float* __restrict__ out)
{
    using namespace cfg;
    using namespace at;
    extern __shared__ uint32_t smd[];

    const int q0 = blockIdx.x * 128;        // global query tile base
    const int bh = blockIdx.y;

    const float* qp = g_q + (size_t)bh * S * HD;
    const float* kp = g_k + (size_t)bh * S * HD;
    const float* vp = g_v + (size_t)bh * S * HD;

    const int t = threadIdx.x;
    const int wid = t >> 5, lane = t & 31;
    const int r = lane >> 2, q = lane & 3;
    const int wr = wid * 16;                // warp row base (0..112)

    const int ldRow = t >> 4;               // 0..15 (+16*i)
    const int ldJ   = (t & 15) * 4;         // word col

    // ---- stage Q into smem (reuses K/V area), lift fragments ----
    {
        uint32_t (*Qs)[KP] = (uint32_t(*)[KP])smd;   // 128 x 68 = 8704 w
        #pragma unroll
        for (int i = 0; i < 8; i++) {
            const int row = ldRow + 16 * i;
            float4 v = *(const float4*)&qp[(size_t)(q0 + row) * HD + ldJ];
            *(uint4*)&Qs[row][ldJ] = cvt4(v);
        }
        __syncthreads();
    }
    uint32_t qa[8][4];
    {
        const uint32_t (*Qs)[KP] = (const uint32_t(*)[KP])smd;
        #pragma unroll
        for (int kk = 0; kk < 8; kk++) {
            qa[kk][0] = Qs[wr + r][kk * 8 + q];
            qa[kk][1] = Qs[wr + r + 8][kk * 8 + q];
            qa[kk][2] = Qs[wr + r][kk * 8 + q + 4];
            qa[kk][3] = Qs[wr + r + 8][kk * 8 + q + 4];
        }
    }
    __syncthreads();

    const int base = q0 - W;                // window radius W
    const int kt_lo = base < 0 ? (-base) >> 6 : 0;
    const int kt_hi = min(9, (S - 64 - base) >> 6);

    // ---- K/V tile staging (64 rows, fully in-sequence by construction) ----
    auto stage = [&](int kt, int buf) {
        const int gb = base + kt * 64;
        uint32_t* Kb = smd + buf * KW;
        uint32_t* Vb = smd + 2 * KW + buf * VW;
        #pragma unroll
        for (int i = 0; i < 4; i++) {
            const int row = ldRow + 16 * i;
            const size_t g = (size_t)(gb + row) * HD + ldJ;
            float4 kv = *(const float4*)&kp[g];
            float4 vv = *(const float4*)&vp[g];
            *(uint4*)&Kb[row * KP + ldJ] = cvt4(kv);
            *(uint4*)&Vb[row * VP + ldJ] = cvt4(vv);
        }
    };
    stage(kt_lo, 0);

    float o[8][4] = {};
    float mrow0 = -1e30f, mrow1 = -1e30f, lsum0 = 0.0f, lsum1 = 0.0f;
    int buf = 0;

    #pragma unroll 1
    for (int kt = kt_lo; kt <= kt_hi; kt++) {
        __syncthreads();
        if (kt < kt_hi) stage(kt + 1, buf ^ 1);

        const uint32_t* Kb = smd + buf * KW;
        const uint32_t* Vb = smd + 2 * KW + buf * VW;

        // ---- S = Q K^T with warp-level group skipping ----
        float sc[8][4];
        #pragma unroll
        for (int nt = 0; nt < 8; nt++) {
            const int y0 = kt * 64 + nt * 8;   // window col of group start
            if (y0 + 7 < wr || y0 > wr + 15 + 2 * W) {
                sc[nt][0] = sc[nt][1] = sc[nt][2] = sc[nt][3] = -1e30f;
                continue;
            }
            sc[nt][0] = sc[nt][1] = sc[nt][2] = sc[nt][3] = 0.0f;
            #pragma unroll
            for (int kk = 0; kk < 8; kk++) {
                uint32_t b[2];
                b[0] = Kb[(nt * 8 + r) * KP + kk * 8 + q];
                b[1] = Kb[(nt * 8 + r) * KP + kk * 8 + q + 4];
                mma_tf32(sc[nt], qa[kk], b);
            }
            const bool full = (y0 >= wr + 15) && (y0 + 7 <= wr + 2 * W);
            if (!full) {
                const int row0 = wr + r, row1 = row0 + 8;
                #pragma unroll
                for (int jj = 0; jj < 2; jj++) {
                    const int col = y0 + 2 * q + jj;
                    if (col < row0 || col > row0 + 2 * W) sc[nt][jj]     = -1e30f;
                    if (col < row1 || col > row1 + 2 * W) sc[nt][2 + jj] = -1e30f;
                }
            }
        }

        // ---- online softmax (rows in lane quads) ----
        float rm0 = -1e30f, rm1 = -1e30f;
        #pragma unroll
        for (int nt = 0; nt < 8; nt++) {
            rm0 = fmaxf(rm0, fmaxf(sc[nt][0], sc[nt][1]));
            rm1 = fmaxf(rm1, fmaxf(sc[nt][2], sc[nt][3]));
        }
        #pragma unroll
        for (int off = 1; off <= 2; off <<= 1) {
            rm0 = fmaxf(rm0, __shfl_xor_sync(0xffffffffu, rm0, off));
            rm1 = fmaxf(rm1, __shfl_xor_sync(0xffffffffu, rm1, off));
        }
        const float mn0 = fmaxf(mrow0, rm0), mn1 = fmaxf(mrow1, rm1);
        const float cr0 = __expf(mrow0 - mn0), cr1 = __expf(mrow1 - mn1);
        float rs0 = 0.0f, rs1 = 0.0f;
        #pragma unroll
        for (int nt = 0; nt < 8; nt++) {
            sc[nt][0] = __expf(sc[nt][0] - mn0);
            sc[nt][1] = __expf(sc[nt][1] - mn0);
            sc[nt][2] = __expf(sc[nt][2] - mn1);
            sc[nt][3] = __expf(sc[nt][3] - mn1);
            rs0 += sc[nt][0] + sc[nt][1];
            rs1 += sc[nt][2] + sc[nt][3];
        }
        #pragma unroll
        for (int off = 1; off <= 2; off <<= 1) {
            rs0 += __shfl_xor_sync(0xffffffffu, rs0, off);
            rs1 += __shfl_xor_sync(0xffffffffu, rs1, off);
        }
        lsum0 = lsum0 * cr0 + rs0;
        lsum1 = lsum1 * cr1 + rs1;
        mrow0 = mn0; mrow1 = mn1;
        #pragma unroll
        for (int nt = 0; nt < 8; nt++) {
            o[nt][0] *= cr0; o[nt][1] *= cr0;
            o[nt][2] *= cr1; o[nt][3] *= cr1;
        }

        // ---- O += P V : quad-shuffle C-frag -> A-frag, no smem for P ----
        const uint32_t srcA = (lane & ~3u) | ((uint32_t)q >> 1);
        const uint32_t srcB = srcA + 2;
        const bool odd = q & 1;
        #pragma unroll
        for (int g = 0; g < 8; g++) {
            const int y0 = kt * 64 + g * 8;
            if (y0 + 7 < wr || y0 > wr + 15 + 2 * W) continue;  // P == 0
            const float p0 = sc[g][0], p1 = sc[g][1];
            const float p2 = sc[g][2], p3 = sc[g][3];
            const float v00 = __shfl_sync(0xffffffffu, p0, srcA);
            const float v01 = __shfl_sync(0xffffffffu, p1, srcA);
            const float v10 = __shfl_sync(0xffffffffu, p0, srcB);
            const float v11 = __shfl_sync(0xffffffffu, p1, srcB);
            const float w00 = __shfl_sync(0xffffffffu, p2, srcA);
            const float w01 = __shfl_sync(0xffffffffu, p3, srcA);
            const float w10 = __shfl_sync(0xffffffffu, p2, srcB);
            const float w11 = __shfl_sync(0xffffffffu, p3, srcB);
            uint32_t pa[4];
            pa[0] = f2tf32(odd ? v01 : v00);
            pa[1] = f2tf32(odd ? w01 : w00);
            pa[2] = f2tf32(odd ? v11 : v10);
            pa[3] = f2tf32(odd ? w11 : w10);
            #pragma unroll
            for (int dg = 0; dg < 8; dg++) {
                uint32_t b[2];
                b[0] = Vb[(g * 8 + q) * VP + dg * 8 + r];
                b[1] = Vb[(g * 8 + q + 4) * VP + dg * 8 + r];
                mma_tf32(o[dg], pa, b);
            }
        }
        buf ^= 1;
    }

    // ---- epilogue ----
    const int b = bh >> 3, h = bh & 7;
    const float inv0 = 1.0f / lsum0, inv1 = 1.0f / lsum1;
    const int p0row = q0 + wr + r;
    const int p1row = p0row + 8;
    #pragma unroll
    for (int dg = 0; dg < 8; dg++) {
        const int col = dg * 8 + 2 * q;
        float2 v0 = make_float2(o[dg][0] * inv0, o[dg][1] * inv0);
        float2 v1 = make_float2(o[dg][2] * inv1, o[dg][3] * inv1);
        *(float2*)&out[((size_t)b * S + p0row) * D + h * HD + col] = v0;
        *(float2*)&out[((size_t)b * S + p1row) * D + h * HD + col] = v1;
    }
}

// ---------------------------------------------------------------------------
extern "C" void kernel_launch(void* const* d_in, const int* in_sizes, int n_in,
                              void* d_out, int out_size)
{
    using namespace cfg;
    (void)in_sizes; (void)n_in; (void)out_size;
    const float* x  = (const float*)d_in[0];
    const float* Wq = (const float*)d_in[1];
    const float* bq = (const float*)d_in[2];
    const float* Wk = (const float*)d_in[3];
    const float* bk = (const float*)d_in[4];
    const float* Wv = (const float*)d_in[5];
    const float* bv = (const float*)d_in[6];
    float* out = (float*)d_out;

    cudaFuncSetAttribute(qkv_mma, cudaFuncAttributeMaxDynamicSharedMemorySize,
                         qk::SMEM_BYTES);
    qkv_mma<<<dim3(D / 128, BS / 128, 3), 256, qk::SMEM_BYTES>>>(
        x, Wq, bq, Wk, bk, Wv, bv);

    cudaFuncSetAttribute(attn, cudaFuncAttributeMaxDynamicSharedMemorySize,
                         at::SMEM_BYTES);
    attn<<<dim3(S / 128, BH), 256, at::SMEM_BYTES>>>(out);
}

// round 6
// speedup vs baseline: 3.4340x; 1.2019x over previous
#include <cuda_runtime.h>
#include <cstdint>

// ---------------- problem constants ----------------
namespace cfg {
constexpr int B  = 2;
constexpr int S  = 8192;
constexpr int D  = 512;
constexpr int H  = 8;
constexpr int W  = 256;
constexpr int HD = 64;
constexpr int BH = B * H;     // 16
constexpr int BS = B * S;     // 16384
}

// scratch for projected q,k,v in (BH, S, HD) layout  (3 x 32 MB)
__device__ float g_q[cfg::BH * cfg::S * cfg::HD];
__device__ float g_k[cfg::BH * cfg::S * cfg::HD];
__device__ float g_v[cfg::BH * cfg::S * cfg::HD];

// ------------------- mma.sync helpers ------------------------
__device__ __forceinline__ uint32_t f2tf32(float f) {
    uint32_t r;
    asm("cvt.rna.tf32.f32 %0, %1;" : "=r"(r) : "f"(f));
    return r;
}
__device__ __forceinline__ void mma_tf32(float* c, const uint32_t* a,
                                         const uint32_t* b) {
    asm volatile(
        "mma.sync.aligned.m16n8k8.row.col.f32.tf32.tf32.f32 "
        "{%0,%1,%2,%3}, {%4,%5,%6,%7}, {%8,%9}, {%0,%1,%2,%3};"
        : "+f"(c[0]), "+f"(c[1]), "+f"(c[2]), "+f"(c[3])
        : "r"(a[0]), "r"(a[1]), "r"(a[2]), "r"(a[3]), "r"(b[0]), "r"(b[1]));
}
__device__ __forceinline__ uint4 cvt4(float4 v) {
    return make_uint4(f2tf32(v.x), f2tf32(v.y), f2tf32(v.z), f2tf32(v.w));
}

// ---------------------------------------------------------------------------
// Kernel 1: QKV projection, tf32 mma.sync, double-buffered smem.
// CTA tile M=128, N=128, K chunk 32. 256 threads = 8 warps (4m x 2n),
// warp tile 32x64. A pitch 36 (banks 4r+q), B pitch 136 (banks 8q+r).
// ---------------------------------------------------------------------------
namespace qk {
constexpr int AP = 36, BP = 136;
constexpr int A_WORDS = 128 * AP;          // 4608
constexpr int B_WORDS = 32 * BP;           // 4352
constexpr int SMEM_BYTES = (2 * A_WORDS + 2 * B_WORDS) * 4;   // 71680
}

__global__ __launch_bounds__(256, 2) void qkv_mma(
    const float* __restrict__ x,
    const float* __restrict__ Wq, const float* __restrict__ bq,
    const float* __restrict__ Wk, const float* __restrict__ bk,
    const float* __restrict__ Wv, const float* __restrict__ bv)
{
    using namespace cfg;
    using namespace qk;
    extern __shared__ uint32_t smq[];

    const int mat = blockIdx.z;
    const float* Wm   = (mat == 0) ? Wq : (mat == 1) ? Wk : Wv;
    const float* bias = (mat == 0) ? bq : (mat == 1) ? bk : bv;
    float* outp       = (mat == 0) ? g_q : (mat == 1) ? g_k : g_v;
    const float scale = (mat == 0) ? 0.125f : 1.0f;

    const int t = threadIdx.x;
    const int wid = t >> 5, lane = t & 31;
    const int wm = wid & 3, wn = wid >> 2;
    const int r = lane >> 2, q = lane & 3;

    const int m0 = blockIdx.y * 128;
    const int n0 = blockIdx.x * 128;

    // loader indices
    const int aR = t >> 3, aJ = t & 7;    // A rows aR + 32*i, col word aJ*4
    const int bR = t >> 5, bJ = t & 31;   // B rows bR + 8*i,  col word bJ*4
    const float* aPtr = x  + (size_t)(m0 + aR) * D + aJ * 4;
    const float* bPtr = Wm + (size_t)bR * D + n0 + bJ * 4;

    float4 ax[4], bx[4];
    #pragma unroll
    for (int i = 0; i < 4; i++) {
        ax[i] = *(const float4*)(aPtr + (size_t)32 * i * D);
        bx[i] = *(const float4*)(bPtr + (size_t)8 * i * D);
    }

    float acc[2][8][4] = {};

    #pragma unroll 1
    for (int ch = 0; ch < 16; ch++) {
        const int buf = ch & 1;
        uint32_t* A  = smq + buf * A_WORDS;
        uint32_t* Bb = smq + 2 * A_WORDS + buf * B_WORDS;

        #pragma unroll
        for (int i = 0; i < 4; i++) {
            *(uint4*)&A[(aR + 32 * i) * AP + aJ * 4]  = cvt4(ax[i]);
            *(uint4*)&Bb[(bR + 8 * i) * BP + bJ * 4]  = cvt4(bx[i]);
        }
        __syncthreads();

        if (ch < 15) {
            const int k0n = (ch + 1) * 32;
            #pragma unroll
            for (int i = 0; i < 4; i++) {
                ax[i] = *(const float4*)(aPtr + (size_t)32 * i * D + k0n);
                bx[i] = *(const float4*)(bPtr + (size_t)(k0n + 8 * i) * D);
            }
        }

        #pragma unroll
        for (int kk = 0; kk < 4; kk++) {
            uint32_t a[2][4];
            #pragma unroll
            for (int mt = 0; mt < 2; mt++) {
                const int rb = wm * 32 + mt * 16;
                a[mt][0] = A[(rb + r) * AP + kk * 8 + q];
                a[mt][1] = A[(rb + r + 8) * AP + kk * 8 + q];
                a[mt][2] = A[(rb + r) * AP + kk * 8 + q + 4];
                a[mt][3] = A[(rb + r + 8) * AP + kk * 8 + q + 4];
            }
            #pragma unroll
            for (int nt = 0; nt < 8; nt++) {
                uint32_t b[2];
                const int nb = wn * 64 + nt * 8 + r;
                b[0] = Bb[(kk * 8 + q) * BP + nb];
                b[1] = Bb[(kk * 8 + q + 4) * BP + nb];
                mma_tf32(acc[0][nt], a[0], b);
                mma_tf32(acc[1][nt], a[1], b);
            }
        }
    }

    // ---- epilogue: bias + scale, head-split layout ----
    #pragma unroll
    for (int mt = 0; mt < 2; mt++) {
        #pragma unroll
        for (int half = 0; half < 2; half++) {
            const int m = m0 + wm * 32 + mt * 16 + r + half * 8;
            const int b = m >> 13, s = m & (S - 1);
            #pragma unroll
            for (int nt = 0; nt < 8; nt++) {
                const int nc = n0 + wn * 64 + nt * 8 + 2 * q;
                const int h = nc >> 6, hc = nc & 63;
                float2 o;
                o.x = (acc[mt][nt][half * 2 + 0] + bias[nc])     * scale;
                o.y = (acc[mt][nt][half * 2 + 1] + bias[nc + 1]) * scale;
                *(float2*)&outp[(((size_t)(b * H + h) * S + s) * HD) + hc] = o;
            }
        }
    }
}

// ---------------------------------------------------------------------------
// Kernel 2: sliding-window attention (radius W=256), flash softmax,
// tf32 mma.sync. 256 threads = 8 warps; 128-query tile; 10 key tiles of 64,
// double-buffered. Q stays in a dedicated smem region (A-fragments loaded per
// tile -> low register pressure -> 2 CTAs/SM). P stays in registers via quad
// shuffles. key = base + col, query = q0 + row, base = q0 - W, band:
// col - row in [0, 2W].
// ---------------------------------------------------------------------------
namespace at {
constexpr int QP = 68, KP = 68, VP = 72;
constexpr int QW = 128 * QP;                // 8704 words
constexpr int KW = 64 * KP;                 // 4352 words / buf
constexpr int VW = 64 * VP;                 // 4608 words / buf
constexpr int SMEM_BYTES = (QW + 2 * KW + 2 * VW) * 4;   // 106496
}

__global__ __launch_bounds__(256, 2) void attn(float* __restrict__ out)
{
    using namespace cfg;
    using namespace at;
    extern __shared__ uint32_t smd[];
    uint32_t* Qs = smd;                     // [128][QP]
    uint32_t* Kbase = smd + QW;             // 2 x [64][KP]
    uint32_t* Vbase = smd + QW + 2 * KW;    // 2 x [64][VP]

    const int q0 = blockIdx.x * 128;        // global query tile base
    const int bh = blockIdx.y;

    const float* qp = g_q + (size_t)bh * S * HD;
    const float* kp = g_k + (size_t)bh * S * HD;
    const float* vp = g_v + (size_t)bh * S * HD;

    const int t = threadIdx.x;
    const int wid = t >> 5, lane = t & 31;
    const int r = lane >> 2, q = lane & 3;
    const int wr = wid * 16;                // warp row base (0..112)

    const int ldRow = t >> 4;               // 0..15 (+16*i)
    const int ldJ   = (t & 15) * 4;         // word col

    // ---- stage Q into its own smem region (persistent for all tiles) ----
    #pragma unroll
    for (int i = 0; i < 8; i++) {
        const int row = ldRow + 16 * i;
        float4 v = *(const float4*)&qp[(size_t)(q0 + row) * HD + ldJ];
        *(uint4*)&Qs[row * QP + ldJ] = cvt4(v);
    }

    const int base = q0 - W;                // window radius W
    const int kt_lo = base < 0 ? (-base) >> 6 : 0;
    const int kt_hi = min(9, (S - 64 - base) >> 6);

    // ---- K/V tile staging (64 rows, fully in-sequence by construction) ----
    auto stage = [&](int kt, int buf) {
        const int gb = base + kt * 64;
        uint32_t* Kb = Kbase + buf * KW;
        uint32_t* Vb = Vbase + buf * VW;
        #pragma unroll
        for (int i = 0; i < 4; i++) {
            const int row = ldRow + 16 * i;
            const size_t g = (size_t)(gb + row) * HD + ldJ;
            float4 kv = *(const float4*)&kp[g];
            float4 vv = *(const float4*)&vp[g];
            *(uint4*)&Kb[row * KP + ldJ] = cvt4(kv);
            *(uint4*)&Vb[row * VP + ldJ] = cvt4(vv);
        }
    };
    stage(kt_lo, 0);

    float o[8][4] = {};
    float mrow0 = -1e30f, mrow1 = -1e30f, lsum0 = 0.0f, lsum1 = 0.0f;
    int buf = 0;

    #pragma unroll 1
    for (int kt = kt_lo; kt <= kt_hi; kt++) {
        __syncthreads();
        if (kt < kt_hi) stage(kt + 1, buf ^ 1);

        const uint32_t* Kb = Kbase + buf * KW;
        const uint32_t* Vb = Vbase + buf * VW;

        // ---- S = Q K^T with warp-level group skipping ----
        float sc[8][4];
        bool act[8];
        #pragma unroll
        for (int nt = 0; nt < 8; nt++) {
            const int y0 = kt * 64 + nt * 8;   // window col of group start
            act[nt] = !(y0 + 7 < wr || y0 > wr + 15 + 2 * W);
            const float init = act[nt] ? 0.0f : -1e30f;
            sc[nt][0] = sc[nt][1] = sc[nt][2] = sc[nt][3] = init;
        }
        #pragma unroll
        for (int kk = 0; kk < 8; kk++) {
            uint32_t a[4];
            a[0] = Qs[(wr + r) * QP + kk * 8 + q];
            a[1] = Qs[(wr + r + 8) * QP + kk * 8 + q];
            a[2] = Qs[(wr + r) * QP + kk * 8 + q + 4];
            a[3] = Qs[(wr + r + 8) * QP + kk * 8 + q + 4];
            #pragma unroll
            for (int nt = 0; nt < 8; nt++) {
                if (!act[nt]) continue;
                uint32_t b[2];
                b[0] = Kb[(nt * 8 + r) * KP + kk * 8 + q];
                b[1] = Kb[(nt * 8 + r) * KP + kk * 8 + q + 4];
                mma_tf32(sc[nt], a, b);
            }
        }
        #pragma unroll
        for (int nt = 0; nt < 8; nt++) {
            if (!act[nt]) continue;
            const int y0 = kt * 64 + nt * 8;
            const bool full = (y0 >= wr + 15) && (y0 + 7 <= wr + 2 * W);
            if (!full) {
                const int row0 = wr + r, row1 = row0 + 8;
                #pragma unroll
                for (int jj = 0; jj < 2; jj++) {
                    const int col = y0 + 2 * q + jj;
                    if (col < row0 || col > row0 + 2 * W) sc[nt][jj]     = -1e30f;
                    if (col < row1 || col > row1 + 2 * W) sc[nt][2 + jj] = -1e30f;
                }
            }
        }

        // ---- online softmax (rows in lane quads) ----
        float rm0 = -1e30f, rm1 = -1e30f;
        #pragma unroll
        for (int nt = 0; nt < 8; nt++) {
            rm0 = fmaxf(rm0, fmaxf(sc[nt][0], sc[nt][1]));
            rm1 = fmaxf(rm1, fmaxf(sc[nt][2], sc[nt][3]));
        }
        #pragma unroll
        for (int off = 1; off <= 2; off <<= 1) {
            rm0 = fmaxf(rm0, __shfl_xor_sync(0xffffffffu, rm0, off));
            rm1 = fmaxf(rm1, __shfl_xor_sync(0xffffffffu, rm1, off));
        }
        const float mn0 = fmaxf(mrow0, rm0), mn1 = fmaxf(mrow1, rm1);
        const float cr0 = __expf(mrow0 - mn0), cr1 = __expf(mrow1 - mn1);
        float rs0 = 0.0f, rs1 = 0.0f;
        #pragma unroll
        for (int nt = 0; nt < 8; nt++) {
            sc[nt][0] = __expf(sc[nt][0] - mn0);
            sc[nt][1] = __expf(sc[nt][1] - mn0);
            sc[nt][2] = __expf(sc[nt][2] - mn1);
            sc[nt][3] = __expf(sc[nt][3] - mn1);
            rs0 += sc[nt][0] + sc[nt][1];
            rs1 += sc[nt][2] + sc[nt][3];
        }
        #pragma unroll
        for (int off = 1; off <= 2; off <<= 1) {
            rs0 += __shfl_xor_sync(0xffffffffu, rs0, off);
            rs1 += __shfl_xor_sync(0xffffffffu, rs1, off);
        }
        lsum0 = lsum0 * cr0 + rs0;
        lsum1 = lsum1 * cr1 + rs1;
        mrow0 = mn0; mrow1 = mn1;
        #pragma unroll
        for (int nt = 0; nt < 8; nt++) {
            o[nt][0] *= cr0; o[nt][1] *= cr0;
            o[nt][2] *= cr1; o[nt][3] *= cr1;
        }

        // ---- O += P V : quad-shuffle C-frag -> A-frag, no smem for P ----
        const uint32_t srcA = (lane & ~3u) | ((uint32_t)q >> 1);
        const uint32_t srcB = srcA + 2;
        const bool odd = q & 1;
        #pragma unroll
        for (int g = 0; g < 8; g++) {
            if (!act[g]) continue;              // P == 0
            const float p0 = sc[g][0], p1 = sc[g][1];
            const float p2 = sc[g][2], p3 = sc[g][3];
            const float v00 = __shfl_sync(0xffffffffu, p0, srcA);
            const float v01 = __shfl_sync(0xffffffffu, p1, srcA);
            const float v10 = __shfl_sync(0xffffffffu, p0, srcB);
            const float v11 = __shfl_sync(0xffffffffu, p1, srcB);
            const float w00 = __shfl_sync(0xffffffffu, p2, srcA);
            const float w01 = __shfl_sync(0xffffffffu, p3, srcA);
            const float w10 = __shfl_sync(0xffffffffu, p2, srcB);
            const float w11 = __shfl_sync(0xffffffffu, p3, srcB);
            uint32_t pa[4];
            pa[0] = f2tf32(odd ? v01 : v00);
            pa[1] = f2tf32(odd ? w01 : w00);
            pa[2] = f2tf32(odd ? v11 : v10);
            pa[3] = f2tf32(odd ? w11 : w10);
            #pragma unroll
            for (int dg = 0; dg < 8; dg++) {
                uint32_t b[2];
                b[0] = Vb[(g * 8 + q) * VP + dg * 8 + r];
                b[1] = Vb[(g * 8 + q + 4) * VP + dg * 8 + r];
                mma_tf32(o[dg], pa, b);
            }
        }
        buf ^= 1;
    }

    // ---- epilogue ----
    const int b = bh >> 3, h = bh & 7;
    const float inv0 = 1.0f / lsum0, inv1 = 1.0f / lsum1;
    const int p0row = q0 + wr + r;
    const int p1row = p0row + 8;
    #pragma unroll
    for (int dg = 0; dg < 8; dg++) {
        const int col = dg * 8 + 2 * q;
        float2 v0 = make_float2(o[dg][0] * inv0, o[dg][1] * inv0);
        float2 v1 = make_float2(o[dg][2] * inv1, o[dg][3] * inv1);
        *(float2*)&out[((size_t)b * S + p0row) * D + h * HD + col] = v0;
        *(float2*)&out[((size_t)b * S + p1row) * D + h * HD + col] = v1;
    }
}

// ---------------------------------------------------------------------------
extern "C" void kernel_launch(void* const* d_in, const int* in_sizes, int n_in,
                              void* d_out, int out_size)
{
    using namespace cfg;
    (void)in_sizes; (void)n_in; (void)out_size;
    const float* x  = (const float*)d_in[0];
    const float* Wq = (const float*)d_in[1];
    const float* bq = (const float*)d_in[2];
    const float* Wk = (const float*)d_in[3];
    const float* bk = (const float*)d_in[4];
    const float* Wv = (const float*)d_in[5];
    const float* bv = (const float*)d_in[6];
    float* out = (float*)d_out;

    cudaFuncSetAttribute(qkv_mma, cudaFuncAttributeMaxDynamicSharedMemorySize,
                         qk::SMEM_BYTES);
    qkv_mma<<<dim3(D / 128, BS / 128, 3), 256, qk::SMEM_BYTES>>>(
        x, Wq, bq, Wk, bk, Wv, bv);

    cudaFuncSetAttribute(attn, cudaFuncAttributeMaxDynamicSharedMemorySize,
                         at::SMEM_BYTES);
    attn<<<dim3(S / 128, BH), 256, at::SMEM_BYTES>>>(out);
}

// round 7
// speedup vs baseline: 5.1121x; 1.4887x over previous
#include <cuda_runtime.h>
#include <cuda_fp16.h>
#include <cstdint>

// ---------------- problem constants ----------------
namespace cfg {
constexpr int B  = 2;
constexpr int S  = 8192;
constexpr int D  = 512;
constexpr int H  = 8;
constexpr int W  = 256;
constexpr int HD = 64;
constexpr int BH = B * H;     // 16
constexpr int BS = B * S;     // 16384
}

// projected q,k,v as fp16 (RNE-rounded at qkv epilogue), (BH, S, HD) layout
__device__ __half g_q[cfg::BH * cfg::S * cfg::HD];
__device__ __half g_k[cfg::BH * cfg::S * cfg::HD];
__device__ __half g_v[cfg::BH * cfg::S * cfg::HD];

// ------------------- helpers ------------------------
__device__ __forceinline__ uint32_t smem_u32(const void* p) {
    uint32_t a;
    asm("{ .reg .u64 t; cvta.to.shared.u64 t, %1; cvt.u32.u64 %0, t; }"
        : "=r"(a) : "l"(p));
    return a;
}
__device__ __forceinline__ void ldmatrix_x4(uint32_t* d, uint32_t addr) {
    asm volatile("ldmatrix.sync.aligned.m8n8.x4.shared.b16 {%0,%1,%2,%3}, [%4];"
                 : "=r"(d[0]), "=r"(d[1]), "=r"(d[2]), "=r"(d[3]) : "r"(addr));
}
__device__ __forceinline__ void ldmatrix_x2(uint32_t* d, uint32_t addr) {
    asm volatile("ldmatrix.sync.aligned.m8n8.x2.shared.b16 {%0,%1}, [%2];"
                 : "=r"(d[0]), "=r"(d[1]) : "r"(addr));
}
__device__ __forceinline__ void ldmatrix_x2t(uint32_t* d, uint32_t addr) {
    asm volatile("ldmatrix.sync.aligned.m8n8.x2.trans.shared.b16 {%0,%1}, [%2];"
                 : "=r"(d[0]), "=r"(d[1]) : "r"(addr));
}
// D(16x8,f32) += A(16x16,f16) * B(16x8,f16)
__device__ __forceinline__ void mma_f16(float* c, const uint32_t* a,
                                        const uint32_t* b) {
    asm volatile(
        "mma.sync.aligned.m16n8k16.row.col.f32.f16.f16.f32 "
        "{%0,%1,%2,%3}, {%4,%5,%6,%7}, {%8,%9}, {%0,%1,%2,%3};"
        : "+f"(c[0]), "+f"(c[1]), "+f"(c[2]), "+f"(c[3])
        : "r"(a[0]), "r"(a[1]), "r"(a[2]), "r"(a[3]), "r"(b[0]), "r"(b[1]));
}
__device__ __forceinline__ uint32_t h2pack(float a, float b) {
    __half2 h = __floats2half2_rn(a, b);    // low = a, high = b
    return *(uint32_t*)&h;
}
__device__ __forceinline__ void cp_async16(uint32_t dst, const void* src) {
    asm volatile("cp.async.cg.shared.global [%0], [%1], 16;"
                 :: "r"(dst), "l"(src) : "memory");
}
__device__ __forceinline__ void cp_commit() {
    asm volatile("cp.async.commit_group;" ::: "memory");
}
__device__ __forceinline__ void cp_wait_all() {
    asm volatile("cp.async.wait_group 0;" ::: "memory");
}

// ---------------------------------------------------------------------------
// Kernel 1: QKV projection, fp16 mma m16n8k16, fp32 accum, double-buffered.
// CTA tile M=128, N=128, K chunk 32. 8 warps (4m x 2n), warp tile 32x64.
// A smem [128][40] halves (pitch 80B), B smem [32][136] halves (pitch 272B).
// ---------------------------------------------------------------------------
namespace qk {
constexpr int AP = 40, BP = 136;               // pitches in halves
constexpr int A_BYTES = 128 * AP * 2;          // 10240
constexpr int B_BYTES = 32 * BP * 2;           // 8704
constexpr int SMEM_BYTES = 2 * (A_BYTES + B_BYTES);  // 37888
}

__global__ __launch_bounds__(256, 2) void qkv_mma(
    const float* __restrict__ x,
    const float* __restrict__ Wq, const float* __restrict__ bq,
    const float* __restrict__ Wk, const float* __restrict__ bk,
    const float* __restrict__ Wv, const float* __restrict__ bv)
{
    using namespace cfg;
    using namespace qk;
    extern __shared__ __align__(16) char smc[];
    const uint32_t sb = smem_u32(smc);

    const int mat = blockIdx.z;
    const float* Wm   = (mat == 0) ? Wq : (mat == 1) ? Wk : Wv;
    const float* bias = (mat == 0) ? bq : (mat == 1) ? bk : bv;
    __half* outp      = (mat == 0) ? g_q : (mat == 1) ? g_k : g_v;
    const float scale = (mat == 0) ? 0.125f : 1.0f;

    const int t = threadIdx.x;
    const int wid = t >> 5, lane = t & 31;
    const int wm = wid & 3, wn = wid >> 2;
    const int r = lane >> 2, q = lane & 3;

    const int m0 = blockIdx.y * 128;
    const int n0 = blockIdx.x * 128;

    // loader indices (A: 128x8 float4 slots; B: 32x32 float4 slots)
    const int aR = t >> 3, aJ = t & 7;
    const int bR = t >> 5, bJ = t & 31;
    const float* aPtr = x  + (size_t)(m0 + aR) * D + aJ * 4;
    const float* bPtr = Wm + (size_t)bR * D + n0 + bJ * 4;

    float4 ax[4], bx[4];
    #pragma unroll
    for (int i = 0; i < 4; i++) {
        ax[i] = *(const float4*)(aPtr + (size_t)32 * i * D);
        bx[i] = *(const float4*)(bPtr + (size_t)8 * i * D);
    }

    // ldmatrix address components (byte offsets within a buffer)
    const int la7 = lane & 7, la8 = ((lane >> 3) & 1) * 8, la16 = (lane >> 4) * 8;
    // A x4: row = wm*32 + mt*16 + la7 + la8 ; colh = kk*16 + la16
    const uint32_t aAddrT = (uint32_t)((wm * 32 + la7 + la8) * AP + la16) * 2;
    // B x2 trans: row = kk*16 + la7 + la8 ; col = wn*64 + nt*8
    const uint32_t bAddrT = (uint32_t)((la7 + la8) * BP + wn * 64) * 2;

    float acc[2][8][4] = {};

    #pragma unroll 1
    for (int ch = 0; ch < 16; ch++) {
        const int buf = ch & 1;
        const uint32_t aBase = sb + buf * A_BYTES;
        const uint32_t bBase = sb + 2 * A_BYTES + buf * B_BYTES;
        __half* Ah = (__half*)(smc + buf * A_BYTES);
        __half* Bh = (__half*)(smc + 2 * A_BYTES + buf * B_BYTES);

        // ---- store staged tiles (fp32 -> fp16 RNE) ----
        #pragma unroll
        for (int i = 0; i < 4; i++) {
            const int arow = aR + 32 * i;
            *(uint2*)&Ah[arow * AP + aJ * 4] =
                make_uint2(h2pack(ax[i].x, ax[i].y), h2pack(ax[i].z, ax[i].w));
            const int brow = bR + 8 * i;
            *(uint2*)&Bh[brow * BP + bJ * 4] =
                make_uint2(h2pack(bx[i].x, bx[i].y), h2pack(bx[i].z, bx[i].w));
        }
        __syncthreads();

        if (ch < 15) {
            const int k0n = (ch + 1) * 32;
            #pragma unroll
            for (int i = 0; i < 4; i++) {
                ax[i] = *(const float4*)(aPtr + (size_t)32 * i * D + k0n);
                bx[i] = *(const float4*)(bPtr + (size_t)(k0n + 8 * i) * D);
            }
        }

        // ---- mma: 2 k-steps of 16 ----
        #pragma unroll
        for (int kk = 0; kk < 2; kk++) {
            uint32_t a0[4], a1[4];
            ldmatrix_x4(a0, aBase + aAddrT + kk * 32);
            ldmatrix_x4(a1, aBase + aAddrT + 16 * AP * 2 + kk * 32);
            #pragma unroll
            for (int nt = 0; nt < 8; nt++) {
                uint32_t b[2];
                ldmatrix_x2t(b, bBase + bAddrT + kk * 16 * BP * 2 + nt * 16);
                mma_f16(acc[0][nt], a0, b);
                mma_f16(acc[1][nt], a1, b);
            }
        }
    }

    // ---- epilogue: bias + scale, RNE to fp16, head-split layout ----
    #pragma unroll
    for (int mt = 0; mt < 2; mt++) {
        #pragma unroll
        for (int half = 0; half < 2; half++) {
            const int m = m0 + wm * 32 + mt * 16 + r + half * 8;
            const int b = m >> 13, s = m & (S - 1);
            #pragma unroll
            for (int nt = 0; nt < 8; nt++) {
                const int nc = n0 + wn * 64 + nt * 8 + 2 * q;
                const int h = nc >> 6, hc = nc & 63;
                uint32_t o = h2pack((acc[mt][nt][half * 2 + 0] + bias[nc])     * scale,
                                    (acc[mt][nt][half * 2 + 1] + bias[nc + 1]) * scale);
                *(uint32_t*)&outp[(((size_t)(b * H + h) * S + s) * HD) + hc] = o;
            }
        }
    }
}

// ---------------------------------------------------------------------------
// Kernel 2: sliding-window attention (radius W=256), flash softmax, fp16 mma.
// 256 threads = 8 warps; 128-query tile; 10 key tiles of 64, cp.async
// double-buffered. Q persistent in smem; QK C-fragments become PV A-fragments
// directly (no shuffles, no smem P). key = base + col, base = q0 - W,
// band: col - row in [0, 2W].
// ---------------------------------------------------------------------------
namespace at {
constexpr int P = 72;                          // pitch in halves (144 B)
constexpr int Q_BYTES = 128 * P * 2;           // 18432
constexpr int KV_BYTES = 64 * P * 2;           // 9216 per buffer
constexpr int OFF_K = Q_BYTES;                 // K0, K1
constexpr int OFF_V = Q_BYTES + 2 * KV_BYTES;  // V0, V1
constexpr int SMEM_BYTES = Q_BYTES + 4 * KV_BYTES;   // 55296
}

__global__ __launch_bounds__(256, 3) void attn(float* __restrict__ out)
{
    using namespace cfg;
    using namespace at;
    extern __shared__ __align__(16) char smc[];
    const uint32_t sb = smem_u32(smc);

    const int q0 = blockIdx.x * 128;
    const int bh = blockIdx.y;

    const __half* qp = g_q + (size_t)bh * S * HD;
    const __half* kp = g_k + (size_t)bh * S * HD;
    const __half* vp = g_v + (size_t)bh * S * HD;

    const int t = threadIdx.x;
    const int lane = t & 31;
    const int r = lane >> 2, q = lane & 3;
    const int wr = (t >> 5) * 16;              // warp row base (0..112)

    const int base = q0 - W;
    const int kt_lo = base < 0 ? (-base) >> 6 : 0;
    const int kt_hi = min(9, (S - 64 - base) >> 6);

    // ---- prologue staging: Q (4 chunks) + K/V(kt_lo) (2+2 chunks) ----
    {
        #pragma unroll
        for (int i = 0; i < 4; i++) {
            const int c = t + 256 * i;           // 0..1023
            const int row = c >> 3, ch = c & 7;
            cp_async16(sb + row * 144 + ch * 16,
                       qp + (size_t)(q0 + row) * HD + ch * 8);
        }
        const int gb = base + kt_lo * 64;
        #pragma unroll
        for (int i = 0; i < 2; i++) {
            const int c = t + 256 * i;           // 0..511
            const int row = c >> 3, ch = c & 7;
            const size_t g = (size_t)(gb + row) * HD + ch * 8;
            cp_async16(sb + OFF_K + row * 144 + ch * 16, kp + g);
            cp_async16(sb + OFF_V + row * 144 + ch * 16, vp + g);
        }
        cp_commit();
    }

    // ldmatrix per-thread address components
    const int la7 = lane & 7, la8 = ((lane >> 3) & 1) * 8, la16 = (lane >> 4) * 8;
    // Q x4: row = wr + la7 + la8, colh = kk*16 + la16
    const uint32_t qAddrT = sb + (uint32_t)((wr + la7 + la8) * P + la16) * 2;
    // K x2 (non-trans): row = nt*8 + la7, colh = kk*16 + la8
    const uint32_t kAddrT = (uint32_t)(la7 * P + la8) * 2;
    // V x2 trans: row = kk*16 + la7 + la8, colh = dg*8
    const uint32_t vAddrT = (uint32_t)((la7 + la8) * P) * 2;

    float o[8][4] = {};
    float mrow0 = -1e30f, mrow1 = -1e30f, lsum0 = 0.0f, lsum1 = 0.0f;
    int buf = 0;

    #pragma unroll 1
    for (int kt = kt_lo; kt <= kt_hi; kt++) {
        cp_wait_all();
        __syncthreads();
        if (kt < kt_hi) {               // prefetch next tile into other buffer
            const int gb = base + (kt + 1) * 64;
            const uint32_t kd = sb + OFF_K + (buf ^ 1) * KV_BYTES;
            const uint32_t vd = sb + OFF_V + (buf ^ 1) * KV_BYTES;
            #pragma unroll
            for (int i = 0; i < 2; i++) {
                const int c = t + 256 * i;
                const int row = c >> 3, ch = c & 7;
                const size_t g = (size_t)(gb + row) * HD + ch * 8;
                cp_async16(kd + row * 144 + ch * 16, kp + g);
                cp_async16(vd + row * 144 + ch * 16, vp + g);
            }
            cp_commit();
        }

        const uint32_t Kb = sb + OFF_K + buf * KV_BYTES;
        const uint32_t Vb = sb + OFF_V + buf * KV_BYTES;

        // ---- S = Q K^T with warp-level group skipping ----
        float sc[8][4];
        bool act[8];
        #pragma unroll
        for (int nt = 0; nt < 8; nt++) {
            const int y0 = kt * 64 + nt * 8;
            act[nt] = !(y0 + 7 < wr || y0 > wr + 15 + 2 * W);
            const float init = act[nt] ? 0.0f : -1e30f;
            sc[nt][0] = sc[nt][1] = sc[nt][2] = sc[nt][3] = init;
        }
        #pragma unroll
        for (int kk = 0; kk < 4; kk++) {
            uint32_t qa[4];
            ldmatrix_x4(qa, qAddrT + kk * 32);
            #pragma unroll
            for (int nt = 0; nt < 8; nt++) {
                if (!act[nt]) continue;
                uint32_t kb[2];
                ldmatrix_x2(kb, Kb + kAddrT + nt * 8 * (P * 2) + kk * 32);
                mma_f16(sc[nt], qa, kb);
            }
        }
        #pragma unroll
        for (int nt = 0; nt < 8; nt++) {
            if (!act[nt]) continue;
            const int y0 = kt * 64 + nt * 8;
            const bool full = (y0 >= wr + 15) && (y0 + 7 <= wr + 2 * W);
            if (!full) {
                const int row0 = wr + r, row1 = row0 + 8;
                #pragma unroll
                for (int jj = 0; jj < 2; jj++) {
                    const int col = y0 + 2 * q + jj;
                    if (col < row0 || col > row0 + 2 * W) sc[nt][jj]     = -1e30f;
                    if (col < row1 || col > row1 + 2 * W) sc[nt][2 + jj] = -1e30f;
                }
            }
        }

        // ---- online softmax (rows live in lane quads) ----
        float rm0 = -1e30f, rm1 = -1e30f;
        #pragma unroll
        for (int nt = 0; nt < 8; nt++) {
            rm0 = fmaxf(rm0, fmaxf(sc[nt][0], sc[nt][1]));
            rm1 = fmaxf(rm1, fmaxf(sc[nt][2], sc[nt][3]));
        }
        #pragma unroll
        for (int off = 1; off <= 2; off <<= 1) {
            rm0 = fmaxf(rm0, __shfl_xor_sync(0xffffffffu, rm0, off));
            rm1 = fmaxf(rm1, __shfl_xor_sync(0xffffffffu, rm1, off));
        }
        const float mn0 = fmaxf(mrow0, rm0), mn1 = fmaxf(mrow1, rm1);
        const float cr0 = __expf(mrow0 - mn0), cr1 = __expf(mrow1 - mn1);
        float rs0 = 0.0f, rs1 = 0.0f;
        #pragma unroll
        for (int nt = 0; nt < 8; nt++) {
            sc[nt][0] = __expf(sc[nt][0] - mn0);
            sc[nt][1] = __expf(sc[nt][1] - mn0);
            sc[nt][2] = __expf(sc[nt][2] - mn1);
            sc[nt][3] = __expf(sc[nt][3] - mn1);
            rs0 += sc[nt][0] + sc[nt][1];
            rs1 += sc[nt][2] + sc[nt][3];
        }
        #pragma unroll
        for (int off = 1; off <= 2; off <<= 1) {
            rs0 += __shfl_xor_sync(0xffffffffu, rs0, off);
            rs1 += __shfl_xor_sync(0xffffffffu, rs1, off);
        }
        lsum0 = lsum0 * cr0 + rs0;
        lsum1 = lsum1 * cr1 + rs1;
        mrow0 = mn0; mrow1 = mn1;
        #pragma unroll
        for (int nt = 0; nt < 8; nt++) {
            o[nt][0] *= cr0; o[nt][1] *= cr0;
            o[nt][2] *= cr1; o[nt][3] *= cr1;
        }

        // ---- O += P V : C-frag pairs ARE the PV A-frag (fp16 packed) ----
        #pragma unroll
        for (int kk = 0; kk < 4; kk++) {        // 16 keys = groups 2kk, 2kk+1
            if (!act[2 * kk] && !act[2 * kk + 1]) continue;
            uint32_t pa[4];
            pa[0] = h2pack(sc[2 * kk][0],     sc[2 * kk][1]);
            pa[1] = h2pack(sc[2 * kk][2],     sc[2 * kk][3]);
            pa[2] = h2pack(sc[2 * kk + 1][0], sc[2 * kk + 1][1]);
            pa[3] = h2pack(sc[2 * kk + 1][2], sc[2 * kk + 1][3]);
            #pragma unroll
            for (int dg = 0; dg < 8; dg++) {
                uint32_t vb[2];
                ldmatrix_x2t(vb, Vb + vAddrT + kk * 16 * (P * 2) + dg * 16);
                mma_f16(o[dg], pa, vb);
            }
        }
        buf ^= 1;
    }

    // ---- epilogue ----
    const int b = bh >> 3, h = bh & 7;
    const float inv0 = 1.0f / lsum0, inv1 = 1.0f / lsum1;
    const int p0row = q0 + wr + r;
    const int p1row = p0row + 8;
    #pragma unroll
    for (int dg = 0; dg < 8; dg++) {
        const int col = dg * 8 + 2 * q;
        float2 v0 = make_float2(o[dg][0] * inv0, o[dg][1] * inv0);
        float2 v1 = make_float2(o[dg][2] * inv1, o[dg][3] * inv1);
        *(float2*)&out[((size_t)b * S + p0row) * D + h * HD + col] = v0;
        *(float2*)&out[((size_t)b * S + p1row) * D + h * HD + col] = v1;
    }
}

// ---------------------------------------------------------------------------
extern "C" void kernel_launch(void* const* d_in, const int* in_sizes, int n_in,
                              void* d_out, int out_size)
{
    using namespace cfg;
    (void)in_sizes; (void)n_in; (void)out_size;
    const float* x  = (const float*)d_in[0];
    const float* Wq = (const float*)d_in[1];
    const float* bq = (const float*)d_in[2];
    const float* Wk = (const float*)d_in[3];
    const float* bk = (const float*)d_in[4];
    const float* Wv = (const float*)d_in[5];
    const float* bv = (const float*)d_in[6];
    float* out = (float*)d_out;

    cudaFuncSetAttribute(qkv_mma, cudaFuncAttributeMaxDynamicSharedMemorySize,
                         qk::SMEM_BYTES);
    qkv_mma<<<dim3(D / 128, BS / 128, 3), 256, qk::SMEM_BYTES>>>(
        x, Wq, bq, Wk, bk, Wv, bv);

    cudaFuncSetAttribute(attn, cudaFuncAttributeMaxDynamicSharedMemorySize,
                         at::SMEM_BYTES);
    attn<<<dim3(S / 128, BH), 256, at::SMEM_BYTES>>>(out);
}